// round 7
// baseline (speedup 1.0000x reference)
#include <cuda_runtime.h>
#include <cuda_bf16.h>

// GCN 2-layer via per-call counting sort (CSR by col), zero aggregation atomics:
//  1. hist: cnt[c]++                         (int atomics)
//  2. scan: off = exclusive_prefix(cnt)      (3 small kernels)
//  3. scatter: sorted (row,w) by col         (int cursor atomics + 8B writes)
//  4. prep: deg[i]=1+sum(sw segment); dinv; y=dinv*x
//  5. aggA: warp/node: agg=sum w*y[r]; a=dinv*(agg+y[i]); h1=relu(a@W1+b1);
//           zz[i]=dinv*(h1@W2)               (fused, no atomics)
//  6. aggB: warp/node: s=sum w*zz[r]; out[i]=b2+dinv[i]*(s+zz[i])
// edge_index is int32 on device (JAX x64 disabled).

#define N_NODES 100000
#define E_MAX   3200000
#define IN_F 8
#define HID_F 64
#define SCAN_T 1024
#define NBLK_MAX 128

__device__ int   g_cnt[N_NODES];
__device__ int   g_off[N_NODES + 1];
__device__ int   g_cur[N_NODES];
__device__ int   g_blk[NBLK_MAX];
__device__ int   g_sr[E_MAX];
__device__ float g_sw[E_MAX];
__device__ float g_dinv[N_NODES];
__device__ __align__(32) float g_y[N_NODES * IN_F];
__device__ float g_zz[N_NODES];

__global__ void k_zero() {
    int i = blockIdx.x * blockDim.x + threadIdx.x;
    if (i < N_NODES) g_cnt[i] = 0;
}

__global__ void k_hist(const int* __restrict__ col, int E) {
    int t = blockIdx.x * blockDim.x + threadIdx.x;
    int e0 = t * 4;
    if (e0 + 3 < E) {
        int4 c4 = *(const int4*)(col + e0);
        atomicAdd(&g_cnt[c4.x], 1);
        atomicAdd(&g_cnt[c4.y], 1);
        atomicAdd(&g_cnt[c4.z], 1);
        atomicAdd(&g_cnt[c4.w], 1);
    } else {
        for (int e = e0; e < E; e++) atomicAdd(&g_cnt[__ldg(col + e)], 1);
    }
}

__global__ void k_scan1() {
    __shared__ int s[SCAN_T];
    int gid = blockIdx.x * SCAN_T + threadIdx.x;
    int v = (gid < N_NODES) ? g_cnt[gid] : 0;
    s[threadIdx.x] = v;
    __syncthreads();
    for (int d = 1; d < SCAN_T; d <<= 1) {
        int t = (threadIdx.x >= d) ? s[threadIdx.x - d] : 0;
        __syncthreads();
        s[threadIdx.x] += t;
        __syncthreads();
    }
    if (gid < N_NODES) g_off[gid] = s[threadIdx.x] - v;  // exclusive
    if (threadIdx.x == SCAN_T - 1) g_blk[blockIdx.x] = s[SCAN_T - 1];
}

__global__ void k_scan2(int nblk) {
    __shared__ int s[NBLK_MAX];
    int v = (threadIdx.x < nblk) ? g_blk[threadIdx.x] : 0;
    s[threadIdx.x] = v;
    __syncthreads();
    for (int d = 1; d < NBLK_MAX; d <<= 1) {
        int t = (threadIdx.x >= d) ? s[threadIdx.x - d] : 0;
        __syncthreads();
        s[threadIdx.x] += t;
        __syncthreads();
    }
    if (threadIdx.x < nblk) g_blk[threadIdx.x] = s[threadIdx.x] - v;  // exclusive
}

__global__ void k_scan3(int E) {
    int i = blockIdx.x * blockDim.x + threadIdx.x;
    if (i < N_NODES) {
        int o = g_off[i] + g_blk[i / SCAN_T];
        g_off[i] = o;
        g_cur[i] = o;
    }
    if (i == 0) g_off[N_NODES] = E;
}

__global__ void k_scatter(const int* __restrict__ row,
                          const int* __restrict__ col,
                          const float* __restrict__ w, int E) {
    int t = blockIdx.x * blockDim.x + threadIdx.x;
    int e0 = t * 4;
    if (e0 + 3 < E) {
        int4 r4 = *(const int4*)(row + e0);
        int4 c4 = *(const int4*)(col + e0);
        float4 w4 = *(const float4*)(w + e0);
        int p;
        p = atomicAdd(&g_cur[c4.x], 1); g_sr[p] = r4.x; g_sw[p] = w4.x;
        p = atomicAdd(&g_cur[c4.y], 1); g_sr[p] = r4.y; g_sw[p] = w4.y;
        p = atomicAdd(&g_cur[c4.z], 1); g_sr[p] = r4.z; g_sw[p] = w4.z;
        p = atomicAdd(&g_cur[c4.w], 1); g_sr[p] = r4.w; g_sw[p] = w4.w;
    } else {
        for (int e = e0; e < E; e++) {
            int c = __ldg(col + e);
            int p = atomicAdd(&g_cur[c], 1);
            g_sr[p] = __ldg(row + e);
            g_sw[p] = __ldg(w + e);
        }
    }
}

// deg = 1 + sum(segment weights); dinv; y = dinv*x
__global__ void k_prep(const float* __restrict__ x) {
    int i = blockIdx.x * blockDim.x + threadIdx.x;
    if (i >= N_NODES) return;
    int p0 = g_off[i], p1 = g_off[i + 1];
    float deg = 1.0f;  // self-loop
    for (int p = p0; p < p1; p++) deg += __ldg(g_sw + p);
    float dinv = rsqrtf(deg);
    g_dinv[i] = dinv;
    const float4* xv = (const float4*)x;
    float4 x0 = __ldg(xv + (size_t)i * 2);
    float4 x1 = __ldg(xv + (size_t)i * 2 + 1);
    ((float4*)g_y)[(size_t)i * 2] =
        make_float4(dinv * x0.x, dinv * x0.y, dinv * x0.z, dinv * x0.w);
    ((float4*)g_y)[(size_t)i * 2 + 1] =
        make_float4(dinv * x1.x, dinv * x1.y, dinv * x1.z, dinv * x1.w);
}

// warp per node: segmented gather-reduce + fused layer-1 GEMM + layer-2 projection
__global__ void __launch_bounds__(512) k_aggA(const float* __restrict__ W1,
                                              const float* __restrict__ b1,
                                              const float* __restrict__ W2) {
    __shared__ float sW1[IN_F * HID_F];
    __shared__ float sb1[HID_F];
    __shared__ float sW2[HID_F];
    for (int t = threadIdx.x; t < IN_F * HID_F; t += blockDim.x) sW1[t] = W1[t];
    if (threadIdx.x < HID_F) {
        sb1[threadIdx.x] = b1[threadIdx.x];
        sW2[threadIdx.x] = W2[threadIdx.x];
    }
    __syncthreads();
    int warp = threadIdx.x >> 5;
    int lane = threadIdx.x & 31;
    int i = blockIdx.x * 16 + warp;
    if (i >= N_NODES) return;
    int p0 = g_off[i], p1 = g_off[i + 1];
    float acc[IN_F] = {0, 0, 0, 0, 0, 0, 0, 0};
    for (int p = p0 + lane; p < p1; p += 32) {
        int r = __ldg(g_sr + p);
        float wt = __ldg(g_sw + p);
        const float4* yv = (const float4*)g_y;
        float4 a0 = __ldg(yv + (size_t)r * 2);
        float4 a1 = __ldg(yv + (size_t)r * 2 + 1);
        acc[0] += wt * a0.x; acc[1] += wt * a0.y;
        acc[2] += wt * a0.z; acc[3] += wt * a0.w;
        acc[4] += wt * a1.x; acc[5] += wt * a1.y;
        acc[6] += wt * a1.z; acc[7] += wt * a1.w;
    }
#pragma unroll
    for (int k = 0; k < IN_F; k++)
#pragma unroll
        for (int m = 16; m > 0; m >>= 1)
            acc[k] += __shfl_xor_sync(0xFFFFFFFFu, acc[k], m);
    // self-loop + norm
    float dinv = g_dinv[i];
    const float4* yv = (const float4*)g_y;
    float4 y0 = __ldg(yv + (size_t)i * 2);
    float4 y1 = __ldg(yv + (size_t)i * 2 + 1);
    float a[IN_F] = {dinv * (acc[0] + y0.x), dinv * (acc[1] + y0.y),
                     dinv * (acc[2] + y0.z), dinv * (acc[3] + y0.w),
                     dinv * (acc[4] + y1.x), dinv * (acc[5] + y1.y),
                     dinv * (acc[6] + y1.z), dinv * (acc[7] + y1.w)};
    // hidden units: lane j and j+32
    float zp = 0.0f;
#pragma unroll
    for (int half = 0; half < 2; half++) {
        int j = lane + half * 32;
        float h = sb1[j];
#pragma unroll
        for (int k = 0; k < IN_F; k++) h = fmaf(a[k], sW1[k * HID_F + j], h);
        h = fmaxf(h, 0.0f);
        zp = fmaf(h, sW2[j], zp);
    }
#pragma unroll
    for (int m = 16; m > 0; m >>= 1)
        zp += __shfl_xor_sync(0xFFFFFFFFu, zp, m);
    if (lane == 0) g_zz[i] = dinv * zp;
}

// warp per node: scalar segmented gather-reduce + epilogue
__global__ void __launch_bounds__(512) k_aggB(const float* __restrict__ b2,
                                              float* __restrict__ out) {
    int warp = threadIdx.x >> 5;
    int lane = threadIdx.x & 31;
    int i = blockIdx.x * 16 + warp;
    if (i >= N_NODES) return;
    int p0 = g_off[i], p1 = g_off[i + 1];
    float s = 0.0f;
    for (int p = p0 + lane; p < p1; p += 32)
        s += __ldg(g_sw + p) * __ldg(g_zz + __ldg(g_sr + p));
#pragma unroll
    for (int m = 16; m > 0; m >>= 1)
        s += __shfl_xor_sync(0xFFFFFFFFu, s, m);
    if (lane == 0)
        out[i] = b2[0] + g_dinv[i] * (s + g_zz[i]);
}

extern "C" void kernel_launch(void* const* d_in, const int* in_sizes, int n_in,
                              void* d_out, int out_size) {
    const float* x = (const float*)d_in[0];
    const int* ei = (const int*)d_in[1];   // int32
    const float* w = (const float*)d_in[2];
    const float* W1 = (const float*)d_in[3];
    const float* b1 = (const float*)d_in[4];
    const float* W2 = (const float*)d_in[5];
    const float* b2 = (const float*)d_in[6];
    float* out = (float*)d_out;

    int E = in_sizes[2];
    const int* row = ei;
    const int* col = ei + E;

    const int T = 256;
    int gNode = (N_NODES + T - 1) / T;
    int gE4 = ((E + 3) / 4 + T - 1) / T;
    int nScanBlk = (N_NODES + SCAN_T - 1) / SCAN_T;  // 98
    int gWarp = (N_NODES + 15) / 16;                 // 16 warps/block

    k_zero<<<gNode, T>>>();
    k_hist<<<gE4, T>>>(col, E);
    k_scan1<<<nScanBlk, SCAN_T>>>();
    k_scan2<<<1, NBLK_MAX>>>(nScanBlk);
    k_scan3<<<gNode, T>>>(E);
    k_scatter<<<gE4, T>>>(row, col, w, E);
    k_prep<<<gNode, T>>>(x);
    k_aggA<<<gWarp, 512>>>(W1, b1, W2);
    k_aggB<<<gWarp, 512>>>(b2, out);
}

// round 8
// speedup vs baseline: 1.6228x; 1.6228x over previous
#include <cuda_runtime.h>
#include <cuda_bf16.h>

// GCN 2-layer, norm-factored, atomic formulation (R4 structure) + PDL overlap:
//   y[i]    = dinv[i]*x[i];  g_agg seeded with y[i] (self-loop)
//   agg[c] += sum_e w_e * y[r_e]           (edgeA: LDG.256 gather + 2x red.v4)
//   a[i]    = dinv[i]*agg[i]; h1=relu(a@W1+b1); zz=dinv*(h1@W2); g_acc seeded zz
//   acc[c] += sum_e w_e * zz[r_e]          (edgeB: scalar atomic)
//   out[i]  = b2 + dinv[i]*acc[i]
// All dependent kernels use programmatic dependent launch: independent loads
// (edge streams, weights, x) run before cudaGridDependencySynchronize().
// edge_index is int32 on device (JAX x64 disabled).

#define N_NODES 100000
#define IN_F 8
#define HID_F 64

__device__ float g_deg[N_NODES];                        // deg -> dinv in place
__device__ __align__(32) float g_y[N_NODES * IN_F];     // dinv*x (gather source)
__device__ __align__(32) float g_agg[N_NODES * IN_F];   // layer-1 agg (seeded y)
__device__ float g_zz[N_NODES];                         // dinv*z (gather source)
__device__ float g_acc[N_NODES];                        // layer-2 agg (seeded zz)

__global__ void k_init() {
    int i = blockIdx.x * blockDim.x + threadIdx.x;
    if (i < N_NODES) g_deg[i] = 1.0f;  // self-loop weight
}

__global__ void k_deg(const int* __restrict__ col,
                      const float* __restrict__ w, int E) {
    int t = blockIdx.x * blockDim.x + threadIdx.x;
    int e0 = t * 8;
    if (e0 + 7 < E) {
        int4 c4a = *(const int4*)(col + e0);
        int4 c4b = *(const int4*)(col + e0 + 4);
        float4 w4a = *(const float4*)(w + e0);
        float4 w4b = *(const float4*)(w + e0 + 4);
        cudaGridDependencySynchronize();   // wait for g_deg init
        atomicAdd(&g_deg[c4a.x], w4a.x);
        atomicAdd(&g_deg[c4a.y], w4a.y);
        atomicAdd(&g_deg[c4a.z], w4a.z);
        atomicAdd(&g_deg[c4a.w], w4a.w);
        atomicAdd(&g_deg[c4b.x], w4b.x);
        atomicAdd(&g_deg[c4b.y], w4b.y);
        atomicAdd(&g_deg[c4b.z], w4b.z);
        atomicAdd(&g_deg[c4b.w], w4b.w);
    } else {
        cudaGridDependencySynchronize();
        for (int e = e0; e < E; e++) atomicAdd(&g_deg[__ldg(col + e)], __ldg(w + e));
    }
}

// dinv; y = dinv*x; seed agg with y (self-loop contribution)
__global__ void k_prep(const float* __restrict__ x) {
    int i = blockIdx.x * blockDim.x + threadIdx.x;
    float4 x0, x1;
    if (i < N_NODES) {  // x is an external input: load before grid sync
        const float4* xv = (const float4*)x;
        x0 = __ldg(xv + (size_t)i * 2);
        x1 = __ldg(xv + (size_t)i * 2 + 1);
    }
    cudaGridDependencySynchronize();       // wait for k_deg atomics
    if (i >= N_NODES) return;
    float d = g_deg[i];
    float dinv = (d > 0.0f) ? rsqrtf(d) : 0.0f;
    g_deg[i] = dinv;
    float4 y0 = make_float4(dinv * x0.x, dinv * x0.y, dinv * x0.z, dinv * x0.w);
    float4 y1 = make_float4(dinv * x1.x, dinv * x1.y, dinv * x1.z, dinv * x1.w);
    ((float4*)g_y)[(size_t)i * 2] = y0;
    ((float4*)g_y)[(size_t)i * 2 + 1] = y1;
    ((float4*)g_agg)[(size_t)i * 2] = y0;
    ((float4*)g_agg)[(size_t)i * 2 + 1] = y1;
}

__device__ __forceinline__ void ld_y8(int r, float* a) {
    asm volatile("ld.global.nc.v8.f32 {%0,%1,%2,%3,%4,%5,%6,%7}, [%8];"
                 : "=f"(a[0]), "=f"(a[1]), "=f"(a[2]), "=f"(a[3]),
                   "=f"(a[4]), "=f"(a[5]), "=f"(a[6]), "=f"(a[7])
                 : "l"(g_y + (size_t)r * IN_F));
}

__device__ __forceinline__ void red_y8(int c, float we, const float* a) {
    float* dst = &g_agg[(size_t)c * IN_F];
    asm volatile("red.global.add.v4.f32 [%0], {%1, %2, %3, %4};"
                 :: "l"(dst), "f"(we * a[0]), "f"(we * a[1]),
                    "f"(we * a[2]), "f"(we * a[3]) : "memory");
    asm volatile("red.global.add.v4.f32 [%0], {%1, %2, %3, %4};"
                 :: "l"(dst + 4), "f"(we * a[4]), "f"(we * a[5]),
                    "f"(we * a[6]), "f"(we * a[7]) : "memory");
}

__global__ void k_edgeA(const int* __restrict__ row,
                        const int* __restrict__ col,
                        const float* __restrict__ w, int E) {
    int t = blockIdx.x * blockDim.x + threadIdx.x;
    int e0 = t * 4;
    if (e0 + 3 < E) {
        int4 r4 = *(const int4*)(row + e0);
        int4 c4 = *(const int4*)(col + e0);
        float4 w4 = *(const float4*)(w + e0);
        cudaGridDependencySynchronize();   // wait for g_y / g_agg seed
        float a0[8], a1[8], a2[8], a3[8];  // batch all gathers first (MLP)
        ld_y8(r4.x, a0);
        ld_y8(r4.y, a1);
        ld_y8(r4.z, a2);
        ld_y8(r4.w, a3);
        red_y8(c4.x, w4.x, a0);
        red_y8(c4.y, w4.y, a1);
        red_y8(c4.z, w4.z, a2);
        red_y8(c4.w, w4.w, a3);
    } else {
        cudaGridDependencySynchronize();
        for (int e = e0; e < E; e++) {
            float a[8];
            ld_y8(__ldg(row + e), a);
            red_y8(__ldg(col + e), __ldg(w + e), a);
        }
    }
}

__global__ void k_node(const float* __restrict__ W1,
                       const float* __restrict__ b1,
                       const float* __restrict__ W2) {
    __shared__ float sW1[IN_F * HID_F];
    __shared__ float sb1[HID_F];
    __shared__ float sW2[HID_F];
    // weights are external inputs: stage them before the grid sync
    for (int t = threadIdx.x; t < IN_F * HID_F; t += blockDim.x) sW1[t] = W1[t];
    if (threadIdx.x < HID_F) {
        sb1[threadIdx.x] = b1[threadIdx.x];
        sW2[threadIdx.x] = W2[threadIdx.x];
    }
    cudaGridDependencySynchronize();       // wait for edgeA reds
    __syncthreads();
    int i = blockIdx.x * blockDim.x + threadIdx.x;
    if (i >= N_NODES) return;
    float dinv = g_deg[i];
    float4 g0 = ((const float4*)g_agg)[(size_t)i * 2];
    float4 g1 = ((const float4*)g_agg)[(size_t)i * 2 + 1];
    float a[IN_F] = {dinv * g0.x, dinv * g0.y, dinv * g0.z, dinv * g0.w,
                     dinv * g1.x, dinv * g1.y, dinv * g1.z, dinv * g1.w};
    float zacc = 0.0f;
#pragma unroll
    for (int j = 0; j < HID_F; j++) {
        float h = sb1[j];
#pragma unroll
        for (int k = 0; k < IN_F; k++) h = fmaf(a[k], sW1[k * HID_F + j], h);
        h = fmaxf(h, 0.0f);
        zacc = fmaf(h, sW2[j], zacc);
    }
    float zz = dinv * zacc;
    g_zz[i] = zz;
    g_acc[i] = zz;  // self-loop seed
}

__global__ void k_edgeB(const int* __restrict__ row,
                        const int* __restrict__ col,
                        const float* __restrict__ w, int E) {
    int t = blockIdx.x * blockDim.x + threadIdx.x;
    int e0 = t * 8;
    if (e0 + 7 < E) {
        int4 r4a = *(const int4*)(row + e0);
        int4 r4b = *(const int4*)(row + e0 + 4);
        int4 c4a = *(const int4*)(col + e0);
        int4 c4b = *(const int4*)(col + e0 + 4);
        float4 w4a = *(const float4*)(w + e0);
        float4 w4b = *(const float4*)(w + e0 + 4);
        cudaGridDependencySynchronize();   // wait for g_zz / g_acc seed
        float z0 = __ldg(g_zz + r4a.x), z1 = __ldg(g_zz + r4a.y);
        float z2 = __ldg(g_zz + r4a.z), z3 = __ldg(g_zz + r4a.w);
        float z4 = __ldg(g_zz + r4b.x), z5 = __ldg(g_zz + r4b.y);
        float z6 = __ldg(g_zz + r4b.z), z7 = __ldg(g_zz + r4b.w);
        atomicAdd(&g_acc[c4a.x], w4a.x * z0);
        atomicAdd(&g_acc[c4a.y], w4a.y * z1);
        atomicAdd(&g_acc[c4a.z], w4a.z * z2);
        atomicAdd(&g_acc[c4a.w], w4a.w * z3);
        atomicAdd(&g_acc[c4b.x], w4b.x * z4);
        atomicAdd(&g_acc[c4b.y], w4b.y * z5);
        atomicAdd(&g_acc[c4b.z], w4b.z * z6);
        atomicAdd(&g_acc[c4b.w], w4b.w * z7);
    } else {
        cudaGridDependencySynchronize();
        for (int e = e0; e < E; e++) {
            int r = __ldg(row + e), c = __ldg(col + e);
            atomicAdd(&g_acc[c], __ldg(w + e) * __ldg(g_zz + r));
        }
    }
}

__global__ void k_final(const float* __restrict__ b2, float* __restrict__ out) {
    int i = blockIdx.x * blockDim.x + threadIdx.x;
    float bias = __ldg(b2);                // external input: load pre-sync
    cudaGridDependencySynchronize();       // wait for edgeB atomics
    if (i < N_NODES)
        out[i] = bias + g_deg[i] * g_acc[i];
}

// launch with programmatic stream serialization (PDL)
static void launch_pdl(const void* func, int grid, int block, void** args) {
    cudaLaunchConfig_t cfg = {};
    cfg.gridDim = dim3(grid, 1, 1);
    cfg.blockDim = dim3(block, 1, 1);
    cfg.dynamicSmemBytes = 0;
    cfg.stream = 0;
    cudaLaunchAttribute at[1];
    at[0].id = cudaLaunchAttributeProgrammaticStreamSerialization;
    at[0].val.programmaticStreamSerializationAllowed = 1;
    cfg.attrs = at;
    cfg.numAttrs = 1;
    cudaLaunchKernelExC(&cfg, func, args);
}

extern "C" void kernel_launch(void* const* d_in, const int* in_sizes, int n_in,
                              void* d_out, int out_size) {
    const float* x = (const float*)d_in[0];
    const int* ei = (const int*)d_in[1];   // int32
    const float* w = (const float*)d_in[2];
    const float* W1 = (const float*)d_in[3];
    const float* b1 = (const float*)d_in[4];
    const float* W2 = (const float*)d_in[5];
    const float* b2 = (const float*)d_in[6];
    float* out = (float*)d_out;

    int E = in_sizes[2];
    const int* row = ei;
    const int* col = ei + E;

    const int T = 256;
    int gNode = (N_NODES + T - 1) / T;
    int gE4 = ((E + 3) / 4 + T - 1) / T;
    int gE8 = ((E + 7) / 8 + T - 1) / T;

    k_init<<<gNode, T>>>();

    { void* a[] = {(void*)&col, (void*)&w, (void*)&E};
      launch_pdl((const void*)k_deg, gE8, T, a); }
    { void* a[] = {(void*)&x};
      launch_pdl((const void*)k_prep, gNode, T, a); }
    { void* a[] = {(void*)&row, (void*)&col, (void*)&w, (void*)&E};
      launch_pdl((const void*)k_edgeA, gE4, T, a); }
    { void* a[] = {(void*)&W1, (void*)&b1, (void*)&W2};
      launch_pdl((const void*)k_node, gNode, T, a); }
    { void* a[] = {(void*)&row, (void*)&col, (void*)&w, (void*)&E};
      launch_pdl((const void*)k_edgeB, gE8, T, a); }
    { void* a[] = {(void*)&b2, (void*)&out};
      launch_pdl((const void*)k_final, gNode, T, a); }
}

// round 9
// speedup vs baseline: 1.8309x; 1.1282x over previous
#include <cuda_runtime.h>
#include <cuda_bf16.h>
#include <cuda_fp16.h>

// GCN 2-layer, norm-factored, atomic formulation + PDL + f16x2 vector reduction:
//   y[i]    = dinv[i]*x[i];  g_agg (f16x8) seeded with y[i] (self-loop)
//   agg[c] += sum_e w_e * y[r_e]     (edgeA: f32 LDG.256 gather + ONE red.v4.f16x2)
//   a[i]    = dinv[i]*agg[i]; h1=relu(a@W1+b1); zz=dinv*(h1@W2); g_acc seeded zz
//   acc[c] += sum_e w_e * zz[r_e]    (edgeB: scalar f32 atomic)
//   out[i]  = b2 + dinv[i]*acc[i]
// g_deg self-resets in k_prep (zero-init at load; zeroed for every graph replay),
// eliminating the init kernel. edge_index is int32 (JAX x64 disabled).

#define N_NODES 100000
#define IN_F 8
#define HID_F 64

__device__ float    g_deg[N_NODES];                    // zero at entry; sum(w); reset
__device__ float    g_dinv[N_NODES];
__device__ __align__(32) float g_y[N_NODES * IN_F];    // f32 gather source
__device__ __align__(16) unsigned int g_agg[N_NODES * 4];  // 4x f16x2 per node
__device__ float    g_zz[N_NODES];
__device__ float    g_acc[N_NODES];

__device__ __forceinline__ unsigned int f2h2(float lo, float hi) {
    unsigned int r;
    asm("cvt.rn.f16x2.f32 %0, %1, %2;" : "=r"(r) : "f"(hi), "f"(lo));
    return r;
}

__global__ void k_deg(const int* __restrict__ col,
                      const float* __restrict__ w, int E) {
    int t = blockIdx.x * blockDim.x + threadIdx.x;
    int e0 = t * 8;
    if (e0 + 7 < E) {
        int4 c4a = *(const int4*)(col + e0);
        int4 c4b = *(const int4*)(col + e0 + 4);
        float4 w4a = *(const float4*)(w + e0);
        float4 w4b = *(const float4*)(w + e0 + 4);
        cudaGridDependencySynchronize();
        atomicAdd(&g_deg[c4a.x], w4a.x);
        atomicAdd(&g_deg[c4a.y], w4a.y);
        atomicAdd(&g_deg[c4a.z], w4a.z);
        atomicAdd(&g_deg[c4a.w], w4a.w);
        atomicAdd(&g_deg[c4b.x], w4b.x);
        atomicAdd(&g_deg[c4b.y], w4b.y);
        atomicAdd(&g_deg[c4b.z], w4b.z);
        atomicAdd(&g_deg[c4b.w], w4b.w);
    } else {
        cudaGridDependencySynchronize();
        for (int e = e0; e < E; e++) atomicAdd(&g_deg[__ldg(col + e)], __ldg(w + e));
    }
}

// dinv; reset deg; y = dinv*x (f32); seed agg with y (f16x2 x4)
__global__ void k_prep(const float* __restrict__ x) {
    int i = blockIdx.x * blockDim.x + threadIdx.x;
    float4 x0, x1;
    if (i < N_NODES) {
        const float4* xv = (const float4*)x;
        x0 = __ldg(xv + (size_t)i * 2);
        x1 = __ldg(xv + (size_t)i * 2 + 1);
    }
    cudaGridDependencySynchronize();
    if (i >= N_NODES) return;
    float dinv = rsqrtf(1.0f + g_deg[i]);  // self-loop weight 1
    g_deg[i] = 0.0f;                       // reset for next graph replay
    g_dinv[i] = dinv;
    float4 y0 = make_float4(dinv * x0.x, dinv * x0.y, dinv * x0.z, dinv * x0.w);
    float4 y1 = make_float4(dinv * x1.x, dinv * x1.y, dinv * x1.z, dinv * x1.w);
    ((float4*)g_y)[(size_t)i * 2] = y0;
    ((float4*)g_y)[(size_t)i * 2 + 1] = y1;
    uint4 s;
    s.x = f2h2(y0.x, y0.y);
    s.y = f2h2(y0.z, y0.w);
    s.z = f2h2(y1.x, y1.y);
    s.w = f2h2(y1.z, y1.w);
    ((uint4*)g_agg)[i] = s;
}

__device__ __forceinline__ void ld_y8(int r, float* a) {
    asm volatile("ld.global.nc.v8.f32 {%0,%1,%2,%3,%4,%5,%6,%7}, [%8];"
                 : "=f"(a[0]), "=f"(a[1]), "=f"(a[2]), "=f"(a[3]),
                   "=f"(a[4]), "=f"(a[5]), "=f"(a[6]), "=f"(a[7])
                 : "l"(g_y + (size_t)r * IN_F));
}

__device__ __forceinline__ void red_h8(int c, float we, const float* a) {
    unsigned int p0 = f2h2(we * a[0], we * a[1]);
    unsigned int p1 = f2h2(we * a[2], we * a[3]);
    unsigned int p2 = f2h2(we * a[4], we * a[5]);
    unsigned int p3 = f2h2(we * a[6], we * a[7]);
    asm volatile("red.global.add.noftz.v4.f16x2 [%0], {%1, %2, %3, %4};"
                 :: "l"(g_agg + (size_t)c * 4), "r"(p0), "r"(p1), "r"(p2), "r"(p3)
                 : "memory");
}

__global__ void k_edgeA(const int* __restrict__ row,
                        const int* __restrict__ col,
                        const float* __restrict__ w, int E) {
    int t = blockIdx.x * blockDim.x + threadIdx.x;
    int e0 = t * 4;
    if (e0 + 3 < E) {
        int4 r4 = *(const int4*)(row + e0);
        int4 c4 = *(const int4*)(col + e0);
        float4 w4 = *(const float4*)(w + e0);
        cudaGridDependencySynchronize();
        float a0[8], a1[8], a2[8], a3[8];  // batch gathers first (MLP)
        ld_y8(r4.x, a0);
        ld_y8(r4.y, a1);
        ld_y8(r4.z, a2);
        ld_y8(r4.w, a3);
        red_h8(c4.x, w4.x, a0);
        red_h8(c4.y, w4.y, a1);
        red_h8(c4.z, w4.z, a2);
        red_h8(c4.w, w4.w, a3);
    } else {
        cudaGridDependencySynchronize();
        for (int e = e0; e < E; e++) {
            float a[8];
            ld_y8(__ldg(row + e), a);
            red_h8(__ldg(col + e), __ldg(w + e), a);
        }
    }
}

__global__ void k_node(const float* __restrict__ W1,
                       const float* __restrict__ b1,
                       const float* __restrict__ W2) {
    __shared__ float sW1[IN_F * HID_F];
    __shared__ float sb1[HID_F];
    __shared__ float sW2[HID_F];
    for (int t = threadIdx.x; t < IN_F * HID_F; t += blockDim.x) sW1[t] = W1[t];
    if (threadIdx.x < HID_F) {
        sb1[threadIdx.x] = b1[threadIdx.x];
        sW2[threadIdx.x] = W2[threadIdx.x];
    }
    cudaGridDependencySynchronize();
    __syncthreads();
    int i = blockIdx.x * blockDim.x + threadIdx.x;
    if (i >= N_NODES) return;
    float dinv = g_dinv[i];
    uint4 u = ((const uint4*)g_agg)[i];
    float2 f0 = __half22float2(*(__half2*)&u.x);
    float2 f1 = __half22float2(*(__half2*)&u.y);
    float2 f2 = __half22float2(*(__half2*)&u.z);
    float2 f3 = __half22float2(*(__half2*)&u.w);
    float a[IN_F] = {dinv * f0.x, dinv * f0.y, dinv * f1.x, dinv * f1.y,
                     dinv * f2.x, dinv * f2.y, dinv * f3.x, dinv * f3.y};
    float zacc = 0.0f;
#pragma unroll
    for (int j = 0; j < HID_F; j++) {
        float h = sb1[j];
#pragma unroll
        for (int k = 0; k < IN_F; k++) h = fmaf(a[k], sW1[k * HID_F + j], h);
        h = fmaxf(h, 0.0f);
        zacc = fmaf(h, sW2[j], zacc);
    }
    float zz = dinv * zacc;
    g_zz[i] = zz;
    g_acc[i] = zz;  // self-loop seed
}

__global__ void k_edgeB(const int* __restrict__ row,
                        const int* __restrict__ col,
                        const float* __restrict__ w, int E) {
    int t = blockIdx.x * blockDim.x + threadIdx.x;
    int e0 = t * 8;
    if (e0 + 7 < E) {
        int4 r4a = *(const int4*)(row + e0);
        int4 r4b = *(const int4*)(row + e0 + 4);
        int4 c4a = *(const int4*)(col + e0);
        int4 c4b = *(const int4*)(col + e0 + 4);
        float4 w4a = *(const float4*)(w + e0);
        float4 w4b = *(const float4*)(w + e0 + 4);
        cudaGridDependencySynchronize();
        float z0 = __ldg(g_zz + r4a.x), z1 = __ldg(g_zz + r4a.y);
        float z2 = __ldg(g_zz + r4a.z), z3 = __ldg(g_zz + r4a.w);
        float z4 = __ldg(g_zz + r4b.x), z5 = __ldg(g_zz + r4b.y);
        float z6 = __ldg(g_zz + r4b.z), z7 = __ldg(g_zz + r4b.w);
        atomicAdd(&g_acc[c4a.x], w4a.x * z0);
        atomicAdd(&g_acc[c4a.y], w4a.y * z1);
        atomicAdd(&g_acc[c4a.z], w4a.z * z2);
        atomicAdd(&g_acc[c4a.w], w4a.w * z3);
        atomicAdd(&g_acc[c4b.x], w4b.x * z4);
        atomicAdd(&g_acc[c4b.y], w4b.y * z5);
        atomicAdd(&g_acc[c4b.z], w4b.z * z6);
        atomicAdd(&g_acc[c4b.w], w4b.w * z7);
    } else {
        cudaGridDependencySynchronize();
        for (int e = e0; e < E; e++) {
            int r = __ldg(row + e), c = __ldg(col + e);
            atomicAdd(&g_acc[c], __ldg(w + e) * __ldg(g_zz + r));
        }
    }
}

__global__ void k_final(const float* __restrict__ b2, float* __restrict__ out) {
    int i = blockIdx.x * blockDim.x + threadIdx.x;
    float bias = __ldg(b2);
    cudaGridDependencySynchronize();
    if (i < N_NODES)
        out[i] = bias + g_dinv[i] * g_acc[i];
}

static void launch_pdl(const void* func, int grid, int block, void** args) {
    cudaLaunchConfig_t cfg = {};
    cfg.gridDim = dim3(grid, 1, 1);
    cfg.blockDim = dim3(block, 1, 1);
    cfg.dynamicSmemBytes = 0;
    cfg.stream = 0;
    cudaLaunchAttribute at[1];
    at[0].id = cudaLaunchAttributeProgrammaticStreamSerialization;
    at[0].val.programmaticStreamSerializationAllowed = 1;
    cfg.attrs = at;
    cfg.numAttrs = 1;
    cudaLaunchKernelExC(&cfg, func, args);
}

extern "C" void kernel_launch(void* const* d_in, const int* in_sizes, int n_in,
                              void* d_out, int out_size) {
    const float* x = (const float*)d_in[0];
    const int* ei = (const int*)d_in[1];   // int32
    const float* w = (const float*)d_in[2];
    const float* W1 = (const float*)d_in[3];
    const float* b1 = (const float*)d_in[4];
    const float* W2 = (const float*)d_in[5];
    const float* b2 = (const float*)d_in[6];
    float* out = (float*)d_out;

    int E = in_sizes[2];
    const int* row = ei;
    const int* col = ei + E;

    const int T = 256;
    int gNode = (N_NODES + T - 1) / T;
    int gE4 = ((E + 3) / 4 + T - 1) / T;
    int gE8 = ((E + 7) / 8 + T - 1) / T;

    { void* a[] = {(void*)&col, (void*)&w, (void*)&E};
      launch_pdl((const void*)k_deg, gE8, T, a); }
    { void* a[] = {(void*)&x};
      launch_pdl((const void*)k_prep, gNode, T, a); }
    { void* a[] = {(void*)&row, (void*)&col, (void*)&w, (void*)&E};
      launch_pdl((const void*)k_edgeA, gE4, T, a); }
    { void* a[] = {(void*)&W1, (void*)&b1, (void*)&W2};
      launch_pdl((const void*)k_node, gNode, T, a); }
    { void* a[] = {(void*)&row, (void*)&col, (void*)&w, (void*)&E};
      launch_pdl((const void*)k_edgeB, gE8, T, a); }
    { void* a[] = {(void*)&b2, (void*)&out};
      launch_pdl((const void*)k_final, gNode, T, a); }
}

// round 11
// speedup vs baseline: 1.8347x; 1.0021x over previous
#include <cuda_runtime.h>
#include <cuda_bf16.h>
#include <cuda_fp16.h>

// GCN 2-layer, norm-factored, atomic formulation + PDL + f16x2 vector reduction
// + packed f32x2 FMA in the node MLP:
//   y[i]    = dinv[i]*x[i];  g_agg (f16x8) seeded with y[i] (self-loop)
//   agg[c] += sum_e w_e * y[r_e]     (edgeA: f32 LDG.256 gather + ONE red.v4.f16x2)
//   a[i]    = dinv[i]*agg[i]; h1=relu(a@W1+b1); zz=dinv*(h1@W2); g_acc seeded zz
//   acc[c] += sum_e w_e * zz[r_e]    (edgeB: scalar f32 atomic)
//   out[i]  = b2 + dinv[i]*acc[i]
// g_deg self-resets in k_prep. edge_index is int32 (JAX x64 disabled).

#define N_NODES 100000
#define IN_F 8
#define HID_F 64

__device__ float    g_deg[N_NODES];                    // zero at entry; sum(w); reset
__device__ float    g_dinv[N_NODES];
__device__ __align__(32) float g_y[N_NODES * IN_F];    // f32 gather source
__device__ __align__(16) unsigned int g_agg[N_NODES * 4];  // 4x f16x2 per node
__device__ float    g_zz[N_NODES];
__device__ float    g_acc[N_NODES];

__device__ __forceinline__ unsigned int f2h2(float lo, float hi) {
    unsigned int r;
    asm("cvt.rn.f16x2.f32 %0, %1, %2;" : "=r"(r) : "f"(hi), "f"(lo));
    return r;
}

__global__ void k_deg(const int* __restrict__ col,
                      const float* __restrict__ w, int E) {
    int t = blockIdx.x * blockDim.x + threadIdx.x;
    int e0 = t * 8;
    if (e0 + 7 < E) {
        int4 c4a = *(const int4*)(col + e0);
        int4 c4b = *(const int4*)(col + e0 + 4);
        float4 w4a = *(const float4*)(w + e0);
        float4 w4b = *(const float4*)(w + e0 + 4);
        cudaGridDependencySynchronize();
        atomicAdd(&g_deg[c4a.x], w4a.x);
        atomicAdd(&g_deg[c4a.y], w4a.y);
        atomicAdd(&g_deg[c4a.z], w4a.z);
        atomicAdd(&g_deg[c4a.w], w4a.w);
        atomicAdd(&g_deg[c4b.x], w4b.x);
        atomicAdd(&g_deg[c4b.y], w4b.y);
        atomicAdd(&g_deg[c4b.z], w4b.z);
        atomicAdd(&g_deg[c4b.w], w4b.w);
    } else {
        cudaGridDependencySynchronize();
        for (int e = e0; e < E; e++) atomicAdd(&g_deg[__ldg(col + e)], __ldg(w + e));
    }
}

// dinv; reset deg; y = dinv*x (f32); seed agg with y (f16x2 x4)
__global__ void k_prep(const float* __restrict__ x) {
    int i = blockIdx.x * blockDim.x + threadIdx.x;
    float4 x0, x1;
    if (i < N_NODES) {
        const float4* xv = (const float4*)x;
        x0 = __ldg(xv + (size_t)i * 2);
        x1 = __ldg(xv + (size_t)i * 2 + 1);
    }
    cudaGridDependencySynchronize();
    if (i >= N_NODES) return;
    float dinv = rsqrtf(1.0f + g_deg[i]);  // self-loop weight 1
    g_deg[i] = 0.0f;                       // reset for next graph replay
    g_dinv[i] = dinv;
    float4 y0 = make_float4(dinv * x0.x, dinv * x0.y, dinv * x0.z, dinv * x0.w);
    float4 y1 = make_float4(dinv * x1.x, dinv * x1.y, dinv * x1.z, dinv * x1.w);
    ((float4*)g_y)[(size_t)i * 2] = y0;
    ((float4*)g_y)[(size_t)i * 2 + 1] = y1;
    uint4 s;
    s.x = f2h2(y0.x, y0.y);
    s.y = f2h2(y0.z, y0.w);
    s.z = f2h2(y1.x, y1.y);
    s.w = f2h2(y1.z, y1.w);
    ((uint4*)g_agg)[i] = s;
}

__device__ __forceinline__ void ld_y8(int r, float* a) {
    asm volatile("ld.global.nc.v8.f32 {%0,%1,%2,%3,%4,%5,%6,%7}, [%8];"
                 : "=f"(a[0]), "=f"(a[1]), "=f"(a[2]), "=f"(a[3]),
                   "=f"(a[4]), "=f"(a[5]), "=f"(a[6]), "=f"(a[7])
                 : "l"(g_y + (size_t)r * IN_F));
}

__device__ __forceinline__ void red_h8(int c, float we, const float* a) {
    unsigned int p0 = f2h2(we * a[0], we * a[1]);
    unsigned int p1 = f2h2(we * a[2], we * a[3]);
    unsigned int p2 = f2h2(we * a[4], we * a[5]);
    unsigned int p3 = f2h2(we * a[6], we * a[7]);
    asm volatile("red.global.add.noftz.v4.f16x2 [%0], {%1, %2, %3, %4};"
                 :: "l"(g_agg + (size_t)c * 4), "r"(p0), "r"(p1), "r"(p2), "r"(p3)
                 : "memory");
}

__global__ void k_edgeA(const int* __restrict__ row,
                        const int* __restrict__ col,
                        const float* __restrict__ w, int E) {
    int t = blockIdx.x * blockDim.x + threadIdx.x;
    int e0 = t * 4;
    if (e0 + 3 < E) {
        int4 r4 = *(const int4*)(row + e0);
        int4 c4 = *(const int4*)(col + e0);
        float4 w4 = *(const float4*)(w + e0);
        cudaGridDependencySynchronize();
        float a0[8], a1[8], a2[8], a3[8];  // batch gathers first (MLP)
        ld_y8(r4.x, a0);
        ld_y8(r4.y, a1);
        ld_y8(r4.z, a2);
        ld_y8(r4.w, a3);
        red_h8(c4.x, w4.x, a0);
        red_h8(c4.y, w4.y, a1);
        red_h8(c4.z, w4.z, a2);
        red_h8(c4.w, w4.w, a3);
    } else {
        cudaGridDependencySynchronize();
        for (int e = e0; e < E; e++) {
            float a[8];
            ld_y8(__ldg(row + e), a);
            red_h8(__ldg(col + e), __ldg(w + e), a);
        }
    }
}

__device__ __forceinline__ unsigned long long packf2(float lo, float hi) {
    unsigned long long d;
    asm("mov.b64 %0, {%1, %2};" : "=l"(d) : "f"(lo), "f"(hi));
    return d;
}

__global__ void __launch_bounds__(256) k_node(const float* __restrict__ W1,
                                              const float* __restrict__ b1,
                                              const float* __restrict__ W2) {
    // weight pairs: W1 row-major [8][64] -> adjacent j are contiguous
    __shared__ __align__(8) float sW1[IN_F * HID_F];
    __shared__ __align__(8) float sb1[HID_F];
    __shared__ __align__(8) float sW2[HID_F];
    for (int t = threadIdx.x; t < IN_F * HID_F; t += blockDim.x) sW1[t] = W1[t];
    if (threadIdx.x < HID_F) {
        sb1[threadIdx.x] = b1[threadIdx.x];
        sW2[threadIdx.x] = W2[threadIdx.x];
    }
    cudaGridDependencySynchronize();
    __syncthreads();
    int i = blockIdx.x * blockDim.x + threadIdx.x;
    if (i >= N_NODES) return;
    float dinv = g_dinv[i];
    uint4 u = ((const uint4*)g_agg)[i];
    float2 f0 = __half22float2(*(__half2*)&u.x);
    float2 f1 = __half22float2(*(__half2*)&u.y);
    float2 f2 = __half22float2(*(__half2*)&u.z);
    float2 f3 = __half22float2(*(__half2*)&u.w);
    float a[IN_F] = {dinv * f0.x, dinv * f0.y, dinv * f1.x, dinv * f1.y,
                     dinv * f2.x, dinv * f2.y, dinv * f3.x, dinv * f3.y};
    unsigned long long a2[IN_F];  // broadcast-packed (a[k], a[k])
#pragma unroll
    for (int k = 0; k < IN_F; k++) a2[k] = packf2(a[k], a[k]);
    const unsigned long long* sW1p = (const unsigned long long*)sW1;
    const unsigned long long* sb1p = (const unsigned long long*)sb1;
    const unsigned long long* sW2p = (const unsigned long long*)sW2;
    float zacc = 0.0f;
#pragma unroll
    for (int jp = 0; jp < HID_F / 2; jp++) {
        unsigned long long h2 = sb1p[jp];
#pragma unroll
        for (int k = 0; k < IN_F; k++) {
            asm("fma.rn.f32x2 %0, %1, %2, %3;"
                : "=l"(h2) : "l"(a2[k]), "l"(sW1p[k * (HID_F / 2) + jp]), "l"(h2));
        }
        float hlo, hhi;
        asm("mov.b64 {%0, %1}, %2;" : "=f"(hlo), "=f"(hhi) : "l"(h2));
        hlo = fmaxf(hlo, 0.0f);
        hhi = fmaxf(hhi, 0.0f);
        float wlo, whi;
        asm("mov.b64 {%0, %1}, %2;" : "=f"(wlo), "=f"(whi) : "l"(sW2p[jp]));
        zacc = fmaf(hlo, wlo, fmaf(hhi, whi, zacc));
    }
    float zz = dinv * zacc;
    g_zz[i] = zz;
    g_acc[i] = zz;  // self-loop seed
}

__global__ void k_edgeB(const int* __restrict__ row,
                        const int* __restrict__ col,
                        const float* __restrict__ w, int E) {
    int t = blockIdx.x * blockDim.x + threadIdx.x;
    int e0 = t * 8;
    if (e0 + 7 < E) {
        int4 r4a = *(const int4*)(row + e0);
        int4 r4b = *(const int4*)(row + e0 + 4);
        int4 c4a = *(const int4*)(col + e0);
        int4 c4b = *(const int4*)(col + e0 + 4);
        float4 w4a = *(const float4*)(w + e0);
        float4 w4b = *(const float4*)(w + e0 + 4);
        cudaGridDependencySynchronize();
        float z0 = __ldg(g_zz + r4a.x), z1 = __ldg(g_zz + r4a.y);
        float z2 = __ldg(g_zz + r4a.z), z3 = __ldg(g_zz + r4a.w);
        float z4 = __ldg(g_zz + r4b.x), z5 = __ldg(g_zz + r4b.y);
        float z6 = __ldg(g_zz + r4b.z), z7 = __ldg(g_zz + r4b.w);
        atomicAdd(&g_acc[c4a.x], w4a.x * z0);
        atomicAdd(&g_acc[c4a.y], w4a.y * z1);
        atomicAdd(&g_acc[c4a.z], w4a.z * z2);
        atomicAdd(&g_acc[c4a.w], w4a.w * z3);
        atomicAdd(&g_acc[c4b.x], w4b.x * z4);
        atomicAdd(&g_acc[c4b.y], w4b.y * z5);
        atomicAdd(&g_acc[c4b.z], w4b.z * z6);
        atomicAdd(&g_acc[c4b.w], w4b.w * z7);
    } else {
        cudaGridDependencySynchronize();
        for (int e = e0; e < E; e++) {
            int r = __ldg(row + e), c = __ldg(col + e);
            atomicAdd(&g_acc[c], __ldg(w + e) * __ldg(g_zz + r));
        }
    }
}

__global__ void k_final(const float* __restrict__ b2, float* __restrict__ out) {
    int i = blockIdx.x * blockDim.x + threadIdx.x;
    float bias = __ldg(b2);
    cudaGridDependencySynchronize();
    if (i < N_NODES)
        out[i] = bias + g_dinv[i] * g_acc[i];
}

static void launch_pdl(const void* func, int grid, int block, void** args) {
    cudaLaunchConfig_t cfg = {};
    cfg.gridDim = dim3(grid, 1, 1);
    cfg.blockDim = dim3(block, 1, 1);
    cfg.dynamicSmemBytes = 0;
    cfg.stream = 0;
    cudaLaunchAttribute at[1];
    at[0].id = cudaLaunchAttributeProgrammaticStreamSerialization;
    at[0].val.programmaticStreamSerializationAllowed = 1;
    cfg.attrs = at;
    cfg.numAttrs = 1;
    cudaLaunchKernelExC(&cfg, func, args);
}

extern "C" void kernel_launch(void* const* d_in, const int* in_sizes, int n_in,
                              void* d_out, int out_size) {
    const float* x = (const float*)d_in[0];
    const int* ei = (const int*)d_in[1];   // int32
    const float* w = (const float*)d_in[2];
    const float* W1 = (const float*)d_in[3];
    const float* b1 = (const float*)d_in[4];
    const float* W2 = (const float*)d_in[5];
    const float* b2 = (const float*)d_in[6];
    float* out = (float*)d_out;

    int E = in_sizes[2];
    const int* row = ei;
    const int* col = ei + E;

    const int T = 256;
    int gNode = (N_NODES + T - 1) / T;
    int gE4 = ((E + 3) / 4 + T - 1) / T;
    int gE8 = ((E + 7) / 8 + T - 1) / T;

    { void* a[] = {(void*)&col, (void*)&w, (void*)&E};
      launch_pdl((const void*)k_deg, gE8, T, a); }
    { void* a[] = {(void*)&x};
      launch_pdl((const void*)k_prep, gNode, T, a); }
    { void* a[] = {(void*)&row, (void*)&col, (void*)&w, (void*)&E};
      launch_pdl((const void*)k_edgeA, gE4, T, a); }
    { void* a[] = {(void*)&W1, (void*)&b1, (void*)&W2};
      launch_pdl((const void*)k_node, gNode, T, a); }
    { void* a[] = {(void*)&row, (void*)&col, (void*)&w, (void*)&E};
      launch_pdl((const void*)k_edgeB, gE8, T, a); }
    { void* a[] = {(void*)&b2, (void*)&out};
      launch_pdl((const void*)k_final, gNode, T, a); }
}